// round 4
// baseline (speedup 1.0000x reference)
#include <cuda_runtime.h>

#define T_DIM 1024
#define F_DIM 256
#define UNITS 32
#define AW    64
#define HALF  32
#define B_DIM 4
#define NROWS (B_DIM * T_DIM)

__device__ float  g_q[NROWS * UNITS];
__device__ float  g_k[NROWS * UNITS];
__device__ float  g_a[NROWS * AW];
__device__ float2 g_Wp[2 * (F_DIM / 2) * UNITS];   // packed (W[2fp][u], W[2fp+1][u])

typedef unsigned long long u64;

__device__ __forceinline__ float tanh_approx(float x) {
    float y;
    asm("tanh.approx.f32 %0, %1;" : "=f"(y) : "f"(x));
    return y;
}
__device__ __forceinline__ u64 ffma2(u64 a, u64 b, u64 c) {
    u64 d;
    asm("fma.rn.f32x2 %0, %1, %2, %3;" : "=l"(d) : "l"(a), "l"(b), "l"(c));
    return d;
}
__device__ __forceinline__ u64 dup2(float w) {
    u64 d;
    asm("mov.b64 %0, {%1, %1};" : "=l"(d) : "r"(__float_as_uint(w)));
    return d;
}
__device__ __forceinline__ float hadd2(u64 v) {
    unsigned lo, hi;
    asm("mov.b64 {%0, %1}, %2;" : "=r"(lo), "=r"(hi) : "l"(v));
    return __uint_as_float(lo) + __uint_as_float(hi);
}

// ---------------------------------------------------------------------------
// Kernel 0: pack Wt/Wx into f-pair-interleaved float2 layout.
// ---------------------------------------------------------------------------
__global__ void __launch_bounds__(256) pack_kernel(
    const float* __restrict__ Wt, const float* __restrict__ Wx)
{
    const int idx = blockIdx.x * 256 + threadIdx.x;      // 8192 float2 total
    const int m   = idx >> 12;                           // 0: Wt, 1: Wx
    const int r   = idx & 4095;                          // fp*32 + u
    const int fp  = r >> 5;
    const int u   = r & 31;
    const float* __restrict__ W = m ? Wx : Wt;
    g_Wp[idx] = make_float2(W[(2 * fp) * UNITS + u], W[(2 * fp + 1) * UNITS + u]);
}

// ---------------------------------------------------------------------------
// Kernel 1: q = x@Wt + bh, k = x@Wx. 512 blocks x 8 warps, 2 rows/warp.
// f32x2 packed math: acc pairs (even-f, odd-f), horizontal add at end.
// ---------------------------------------------------------------------------
__global__ void __launch_bounds__(256) qk_kernel(
    const float* __restrict__ x, const float* __restrict__ bh)
{
    __shared__ float xs[8 * F_DIM];                      // 8 rows = 8KB

    const int tid = threadIdx.x;
    const int r0  = blockIdx.x * 8;

    const float4* xg  = reinterpret_cast<const float4*>(x) + (size_t)r0 * (F_DIM / 4);
    float4*       xs4 = reinterpret_cast<float4*>(xs);
    xs4[tid]       = xg[tid];
    xs4[tid + 256] = xg[tid + 256];
    __syncthreads();

    const int  wid  = tid >> 5;
    const int  lane = tid & 31;
    const bool is_q = (wid < 4);
    const int  rb   = (wid & 3) * 2;

    const u64* __restrict__ Wp =
        reinterpret_cast<const u64*>(g_Wp) + (is_q ? 0 : (F_DIM / 2) * UNITS);
    const u64* __restrict__ x0 = reinterpret_cast<const u64*>(xs + (rb + 0) * F_DIM);
    const u64* __restrict__ x1 = reinterpret_cast<const u64*>(xs + (rb + 1) * F_DIM);

    u64 acc0 = 0ull, acc1 = 0ull;                        // (0.f, 0.f)

    #pragma unroll 8
    for (int f4 = 0; f4 < F_DIM / 4; f4++) {
        const int fp = 2 * f4;
        const u64 w01 = Wp[(fp + 0) * UNITS + lane];     // LDG.64, coalesced
        const u64 w23 = Wp[(fp + 1) * UNITS + lane];
        const u64 v0a = x0[fp], v0b = x0[fp + 1];        // LDS.64 broadcast
        const u64 v1a = x1[fp], v1b = x1[fp + 1];
        acc0 = ffma2(v0a, w01, acc0);
        acc0 = ffma2(v0b, w23, acc0);
        acc1 = ffma2(v1a, w01, acc1);
        acc1 = ffma2(v1b, w23, acc1);
    }

    const float bias = is_q ? bh[lane] : 0.f;
    float* __restrict__ G = is_q ? g_q : g_k;
    G[(size_t)(r0 + rb + 0) * UNITS + lane] = hadd2(acc0) + bias;
    G[(size_t)(r0 + rb + 1) * UNITS + lane] = hadd2(acc1) + bias;
}

// ---------------------------------------------------------------------------
// Kernel 2: band logits + softmax -> g_a. 8 t per block, grid (128, B).
// ---------------------------------------------------------------------------
__global__ void __launch_bounds__(256) weights_kernel(
    const float* __restrict__ Wa, const float* __restrict__ ba)
{
    const int b  = blockIdx.y;
    const int t0 = blockIdx.x * 8;
    const int sbase = t0 - HALF;
    const int SR = 8 + AW - 1;                   // 71 staged k rows

    __shared__ float ks[71 * 33];
    __shared__ float qs[8 * UNITS];
    __shared__ float was[UNITS];
    __shared__ float es[8 * AW];

    const int tid = threadIdx.x;

    for (int idx = tid; idx < SR * UNITS; idx += 256) {
        const int srel = idx >> 5, u = idx & 31;
        int s = sbase + srel;
        s = min(max(s, 0), T_DIM - 1);
        ks[srel * 33 + u] = g_k[(size_t)(b * T_DIM + s) * UNITS + u];
    }
    if (tid < 8 * UNITS)
        qs[tid] = g_q[(size_t)(b * T_DIM + t0) * UNITS + tid];
    if (tid < UNITS) was[tid] = Wa[tid];
    __syncthreads();

    const float bav = ba[0];

    #pragma unroll
    for (int l = 0; l < 2; l++) {
        const int idx = tid + l * 256;
        const int tl  = idx >> 6;
        const int j   = idx & 63;
        const int s   = t0 + tl - HALF + j;
        float e = -1e30f;
        if (s >= 0 && s < T_DIM) {
            const int srel = tl + j;
            float acc = 0.f;
            #pragma unroll
            for (int u = 0; u < UNITS; u++)
                acc += was[u] * tanh_approx(qs[tl * UNITS + u] + ks[srel * 33 + u]);
            e = acc + bav;
        }
        es[tl * AW + j] = e;
    }
    __syncthreads();

    const int wid = tid >> 5, lane = tid & 31;
    {
        const float e0 = es[wid * AW + lane];
        const float e1 = es[wid * AW + lane + 32];
        float m = fmaxf(e0, e1);
        #pragma unroll
        for (int o = 16; o; o >>= 1)
            m = fmaxf(m, __shfl_xor_sync(0xffffffffu, m, o));
        const float p0 = __expf(e0 - m);
        const float p1 = __expf(e1 - m);
        float sum = p0 + p1;
        #pragma unroll
        for (int o = 16; o; o >>= 1)
            sum += __shfl_xor_sync(0xffffffffu, sum, o);
        const float inv = 1.f / sum;
        const size_t row = (size_t)(b * T_DIM + t0 + wid) * AW;
        g_a[row + lane]      = p0 * inv;
        g_a[row + lane + 32] = p1 * inv;
    }
}

// ---------------------------------------------------------------------------
// Kernel 3: v = banded a @ x, f32x2 math. Thread = (2 t, 4 f).
// grid (64, B, 2), block 256.
// ---------------------------------------------------------------------------
__global__ void __launch_bounds__(256) out_kernel(
    const float* __restrict__ x, float* __restrict__ out)
{
    const int b   = blockIdx.y;
    const int t0  = blockIdx.x * 16;
    const int fb4 = blockIdx.z * 32;

    __shared__ float as[16 * AW];
    const int tid = threadIdx.x;
    #pragma unroll
    for (int l = 0; l < 4; l++)
        as[tid + l * 256] = g_a[(size_t)(b * T_DIM + t0) * AW + tid + l * 256];
    __syncthreads();

    const int tg    = tid >> 5;
    const int f4    = fb4 + (tid & 31);
    const int tbase = t0 + tg * 2;

    const u64* __restrict__ xg =
        reinterpret_cast<const u64*>(x) + (size_t)b * T_DIM * (F_DIM / 2);
    const float* aw0 = as + (tg * 2 + 0) * AW;
    const float* aw1 = as + (tg * 2 + 1) * AW;

    u64 acc0a = 0ull, acc0b = 0ull, acc1a = 0ull, acc1b = 0ull;

    #pragma unroll 4
    for (int i = 0; i < AW + 1; i++) {           // union window: 65 rows
        int s = tbase - HALF + i;
        s = min(max(s, 0), T_DIM - 1);           // invalid s has weight 0
        const u64 xa = xg[(size_t)s * (F_DIM / 2) + f4 * 2];
        const u64 xb = xg[(size_t)s * (F_DIM / 2) + f4 * 2 + 1];
        const float w0 = (i < AW) ? aw0[i] : 0.f;
        const float w1 = (i > 0)  ? aw1[i - 1] : 0.f;
        const u64 w0p = dup2(w0);
        const u64 w1p = dup2(w1);
        acc0a = ffma2(xa, w0p, acc0a);
        acc0b = ffma2(xb, w0p, acc0b);
        acc1a = ffma2(xa, w1p, acc1a);
        acc1b = ffma2(xb, w1p, acc1b);
    }

    u64* __restrict__ og =
        reinterpret_cast<u64*>(out) + (size_t)b * T_DIM * (F_DIM / 2);
    og[(size_t)(tbase + 0) * (F_DIM / 2) + f4 * 2]     = acc0a;
    og[(size_t)(tbase + 0) * (F_DIM / 2) + f4 * 2 + 1] = acc0b;
    og[(size_t)(tbase + 1) * (F_DIM / 2) + f4 * 2]     = acc1a;
    og[(size_t)(tbase + 1) * (F_DIM / 2) + f4 * 2 + 1] = acc1b;
}

extern "C" void kernel_launch(void* const* d_in, const int* in_sizes, int n_in,
                              void* d_out, int out_size)
{
    const float* x  = (const float*)d_in[0];
    const float* Wt = (const float*)d_in[1];
    const float* Wx = (const float*)d_in[2];
    const float* bh = (const float*)d_in[3];
    const float* Wa = (const float*)d_in[4];
    const float* ba = (const float*)d_in[5];
    float* out = (float*)d_out;

    pack_kernel<<<32, 256>>>(Wt, Wx);
    qk_kernel<<<NROWS / 8, 256>>>(x, bh);
    weights_kernel<<<dim3(T_DIM / 8, B_DIM), 256>>>(Wa, ba);
    out_kernel<<<dim3(T_DIM / 16, B_DIM, 2), 256>>>(x, out);
}

// round 5
// speedup vs baseline: 1.0738x; 1.0738x over previous
#include <cuda_runtime.h>

#define T_DIM 1024
#define F_DIM 256
#define F4    (F_DIM / 4)
#define UNITS 32
#define AW    64
#define HALF  32
#define B_DIM 4
#define NROWS (B_DIM * T_DIM)

__device__ float  g_q[NROWS * UNITS];
__device__ float  g_k[NROWS * UNITS];
__device__ float2 g_a2[NROWS * AW];                // duplicated (a, a) pairs
__device__ float2 g_Wp[2 * (F_DIM / 2) * UNITS];   // packed (W[2fp][u], W[2fp+1][u])

typedef unsigned long long u64;

__device__ __forceinline__ float tanh_approx(float x) {
    float y;
    asm("tanh.approx.f32 %0, %1;" : "=f"(y) : "f"(x));
    return y;
}
__device__ __forceinline__ u64 ffma2(u64 a, u64 b, u64 c) {
    u64 d;
    asm("fma.rn.f32x2 %0, %1, %2, %3;" : "=l"(d) : "l"(a), "l"(b), "l"(c));
    return d;
}
__device__ __forceinline__ float hadd2(u64 v) {
    unsigned lo, hi;
    asm("mov.b64 {%0, %1}, %2;" : "=r"(lo), "=r"(hi) : "l"(v));
    return __uint_as_float(lo) + __uint_as_float(hi);
}
// float4 -> two aligned f32x2 register pairs (movs elided by ptxas when aligned)
__device__ __forceinline__ void f4_to_u64(float4 v, u64& a, u64& b) {
    asm("mov.b64 %0, {%2, %3};\n\tmov.b64 %1, {%4, %5};"
        : "=l"(a), "=l"(b) : "f"(v.x), "f"(v.y), "f"(v.z), "f"(v.w));
}
__device__ __forceinline__ void u64_to_f4(u64 a, u64 b, float4& v) {
    asm("mov.b64 {%0, %1}, %4;\n\tmov.b64 {%2, %3}, %5;"
        : "=f"(v.x), "=f"(v.y), "=f"(v.z), "=f"(v.w) : "l"(a), "l"(b));
}

// ---------------------------------------------------------------------------
// Kernel 0: pack Wt/Wx into f-pair-interleaved float2 layout.
// ---------------------------------------------------------------------------
__global__ void __launch_bounds__(256) pack_kernel(
    const float* __restrict__ Wt, const float* __restrict__ Wx)
{
    const int idx = blockIdx.x * 256 + threadIdx.x;      // 8192 float2 total
    const int m   = idx >> 12;
    const int r   = idx & 4095;
    const int fp  = r >> 5;
    const int u   = r & 31;
    const float* __restrict__ W = m ? Wx : Wt;
    g_Wp[idx] = make_float2(W[(2 * fp) * UNITS + u], W[(2 * fp + 1) * UNITS + u]);
}

// ---------------------------------------------------------------------------
// Kernel 1: q = x@Wt + bh, k = x@Wx. 512 blocks x 8 warps, 2 rows/warp.
// Per f4 iter: 2 LDG.64 (W) + 2 LDS.128 (x) + 4 FFMA2.
// ---------------------------------------------------------------------------
__global__ void __launch_bounds__(256) qk_kernel(
    const float* __restrict__ x, const float* __restrict__ bh)
{
    __shared__ float4 xs4[8 * F4];                       // 8 rows = 8KB

    const int tid = threadIdx.x;
    const int r0  = blockIdx.x * 8;

    const float4* xg = reinterpret_cast<const float4*>(x) + (size_t)r0 * F4;
    xs4[tid]       = xg[tid];
    xs4[tid + 256] = xg[tid + 256];
    __syncthreads();

    const int  wid  = tid >> 5;
    const int  lane = tid & 31;
    const bool is_q = (wid < 4);
    const int  rb   = (wid & 3) * 2;

    const u64* __restrict__ Wp =
        reinterpret_cast<const u64*>(g_Wp) + (is_q ? 0 : (F_DIM / 2) * UNITS);
    const float4* __restrict__ x0 = xs4 + (rb + 0) * F4;
    const float4* __restrict__ x1 = xs4 + (rb + 1) * F4;

    u64 acc0 = 0ull, acc1 = 0ull;

    #pragma unroll 8
    for (int f4 = 0; f4 < F4; f4++) {
        const u64 w01 = Wp[(2 * f4 + 0) * UNITS + lane];
        const u64 w23 = Wp[(2 * f4 + 1) * UNITS + lane];
        u64 v0a, v0b, v1a, v1b;
        f4_to_u64(x0[f4], v0a, v0b);                     // LDS.128
        f4_to_u64(x1[f4], v1a, v1b);
        acc0 = ffma2(v0a, w01, acc0);
        acc0 = ffma2(v0b, w23, acc0);
        acc1 = ffma2(v1a, w01, acc1);
        acc1 = ffma2(v1b, w23, acc1);
    }

    const float bias = is_q ? bh[lane] : 0.f;
    float* __restrict__ G = is_q ? g_q : g_k;
    G[(size_t)(r0 + rb + 0) * UNITS + lane] = hadd2(acc0) + bias;
    G[(size_t)(r0 + rb + 1) * UNITS + lane] = hadd2(acc1) + bias;
}

// ---------------------------------------------------------------------------
// Kernel 2: band logits + softmax -> g_a2 (duplicated pairs).
// ---------------------------------------------------------------------------
__global__ void __launch_bounds__(256) weights_kernel(
    const float* __restrict__ Wa, const float* __restrict__ ba)
{
    const int b  = blockIdx.y;
    const int t0 = blockIdx.x * 8;
    const int sbase = t0 - HALF;
    const int SR = 8 + AW - 1;                   // 71 staged k rows

    __shared__ float ks[71 * 33];
    __shared__ float qs[8 * UNITS];
    __shared__ float was[UNITS];
    __shared__ float es[8 * AW];

    const int tid = threadIdx.x;

    for (int idx = tid; idx < SR * UNITS; idx += 256) {
        const int srel = idx >> 5, u = idx & 31;
        int s = sbase + srel;
        s = min(max(s, 0), T_DIM - 1);
        ks[srel * 33 + u] = g_k[(size_t)(b * T_DIM + s) * UNITS + u];
    }
    if (tid < 8 * UNITS)
        qs[tid] = g_q[(size_t)(b * T_DIM + t0) * UNITS + tid];
    if (tid < UNITS) was[tid] = Wa[tid];
    __syncthreads();

    const float bav = ba[0];

    #pragma unroll
    for (int l = 0; l < 2; l++) {
        const int idx = tid + l * 256;
        const int tl  = idx >> 6;
        const int j   = idx & 63;
        const int s   = t0 + tl - HALF + j;
        float e = -1e30f;
        if (s >= 0 && s < T_DIM) {
            const int srel = tl + j;
            float acc = 0.f;
            #pragma unroll
            for (int u = 0; u < UNITS; u++)
                acc += was[u] * tanh_approx(qs[tl * UNITS + u] + ks[srel * 33 + u]);
            e = acc + bav;
        }
        es[tl * AW + j] = e;
    }
    __syncthreads();

    const int wid = tid >> 5, lane = tid & 31;
    {
        const float e0 = es[wid * AW + lane];
        const float e1 = es[wid * AW + lane + 32];
        float m = fmaxf(e0, e1);
        #pragma unroll
        for (int o = 16; o; o >>= 1)
            m = fmaxf(m, __shfl_xor_sync(0xffffffffu, m, o));
        const float p0 = __expf(e0 - m);
        const float p1 = __expf(e1 - m);
        float sum = p0 + p1;
        #pragma unroll
        for (int o = 16; o; o >>= 1)
            sum += __shfl_xor_sync(0xffffffffu, sum, o);
        const float inv = 1.f / sum;
        const size_t row = (size_t)(b * T_DIM + t0 + wid) * AW;
        const float a0 = p0 * inv, a1 = p1 * inv;
        g_a2[row + lane]      = make_float2(a0, a0);
        g_a2[row + lane + 32] = make_float2(a1, a1);
    }
}

// ---------------------------------------------------------------------------
// Kernel 3: v = banded a @ x. Thread = (2 t, 1 float4). grid (64, B, 2).
// Interior fast path: rolling register, no clamps; 8 issues / 16 MACs.
// ---------------------------------------------------------------------------
__global__ void __launch_bounds__(256) out_kernel(
    const float* __restrict__ x, float* __restrict__ out)
{
    const int b   = blockIdx.y;
    const int t0  = blockIdx.x * 16;
    const int fb4 = blockIdx.z * 32;

    __shared__ float2 as2[16 * AW];              // 8KB duplicated weights
    const int tid = threadIdx.x;
    {
        const float4* src = reinterpret_cast<const float4*>(
            g_a2 + (size_t)(b * T_DIM + t0) * AW);
        float4* dst = reinterpret_cast<float4*>(as2);
        dst[tid]       = src[tid];
        dst[tid + 256] = src[tid + 256];
    }
    __syncthreads();

    const int tg    = tid >> 5;
    const int f4    = fb4 + (tid & 31);
    const int tbase = t0 + tg * 2;

    const float4* __restrict__ xg4 =
        reinterpret_cast<const float4*>(x) + (size_t)b * T_DIM * F4;
    const u64* aw0 = reinterpret_cast<const u64*>(as2 + (tg * 2 + 0) * AW);
    const u64* aw1 = reinterpret_cast<const u64*>(as2 + (tg * 2 + 1) * AW);

    u64 acc0a = 0ull, acc0b = 0ull, acc1a = 0ull, acc1b = 0ull;

    if (t0 >= HALF && t0 + 15 + HALF < T_DIM) {
        // ---- interior fast path ----
        const float4* xp = xg4 + (size_t)(tbase - HALF) * F4 + f4;
        u64 ra, rb;
        f4_to_u64(*xp, ra, rb);
        xp += F4;
        #pragma unroll 8
        for (int i = 0; i < AW; i++) {
            u64 na, nb;
            f4_to_u64(*xp, na, nb);              // LDG.128
            xp += F4;
            const u64 w0 = aw0[i];               // LDS.64 (dup pair)
            const u64 w1 = aw1[i];
            acc0a = ffma2(ra, w0, acc0a);
            acc0b = ffma2(rb, w0, acc0b);
            acc1a = ffma2(na, w1, acc1a);
            acc1b = ffma2(nb, w1, acc1b);
            ra = na; rb = nb;
        }
    } else {
        // ---- boundary path (clamped; invalid s has weight 0) ----
        #pragma unroll 4
        for (int i = 0; i < AW + 1; i++) {
            int s = tbase - HALF + i;
            s = min(max(s, 0), T_DIM - 1);
            u64 xa, xb;
            f4_to_u64(xg4[(size_t)s * F4 + f4], xa, xb);
            const u64 w0 = (i < AW) ? aw0[i]     : 0ull;
            const u64 w1 = (i > 0)  ? aw1[i - 1] : 0ull;
            acc0a = ffma2(xa, w0, acc0a);
            acc0b = ffma2(xb, w0, acc0b);
            acc1a = ffma2(xa, w1, acc1a);
            acc1b = ffma2(xb, w1, acc1b);
        }
    }

    float4 o0, o1;
    u64_to_f4(acc0a, acc0b, o0);
    u64_to_f4(acc1a, acc1b, o1);
    float4* __restrict__ og =
        reinterpret_cast<float4*>(out) + (size_t)b * T_DIM * F4;
    og[(size_t)(tbase + 0) * F4 + f4] = o0;
    og[(size_t)(tbase + 1) * F4 + f4] = o1;
}

extern "C" void kernel_launch(void* const* d_in, const int* in_sizes, int n_in,
                              void* d_out, int out_size)
{
    const float* x  = (const float*)d_in[0];
    const float* Wt = (const float*)d_in[1];
    const float* Wx = (const float*)d_in[2];
    const float* bh = (const float*)d_in[3];
    const float* Wa = (const float*)d_in[4];
    const float* ba = (const float*)d_in[5];
    float* out = (float*)d_out;

    pack_kernel<<<32, 256>>>(Wt, Wx);
    qk_kernel<<<NROWS / 8, 256>>>(x, bh);
    weights_kernel<<<dim3(T_DIM / 8, B_DIM), 256>>>(Wa, ba);
    out_kernel<<<dim3(T_DIM / 16, B_DIM, 2), 256>>>(x, out);
}